// round 10
// baseline (speedup 1.0000x reference)
#include <cuda_runtime.h>
#include <cuda_bf16.h>

// Shapes (fixed by problem)
#define Bb 32
#define Nn 32
#define Ll 512
#define Mm 64
#define Ff 64
#define EPSV 1e-8f

#define CHUNK_L 16
#define NCHUNK  (Ll / CHUNK_L)   // 32

// Scratch (no cudaMalloc allowed): alpha stored PRE-DUPLICATED as float2 (a,a)
// so the gemm cp.asyncs straight into smem and feeds fma.rn.f32x2 directly.
__device__ float2 g_alpha_dup[Nn * Ll * Mm];   // 8 MB
__device__ float  g_rdenom[Nn * Mm];

// ---------------------------------------------------------------------------
// Kernel 1: alpha[n,l,m] = sigmoid((tr-t)/k)*sigmoid((t-tl)/k), k=softplus(kappa)
// + fused denominator. grid 32 (one per n), 256 threads: m=tid>>2, lq=tid&3.
// ---------------------------------------------------------------------------
__global__ void __launch_bounds__(256) alpha_kernel(
    const float* __restrict__ t,       // [L,1]
    const float* __restrict__ t_left,  // [N,M]
    const float* __restrict__ t_right, // [N,M]
    const float* __restrict__ kappa)   // [N,1]
{
    const int n  = blockIdx.x;
    const int tid = threadIdx.x;
    const int m  = tid >> 2;
    const int lq = tid & 3;

    const float ka = kappa[n];
    const float k  = (ka > 20.0f) ? ka : log1pf(expf(ka));
    const float invk = 1.0f / k;
    const float tlv = t_left [n * Mm + m];
    const float trv = t_right[n * Mm + m];

    float2* __restrict__ ad = g_alpha_dup + (size_t)(n * Ll) * Mm;

    float sum = 0.0f;
#pragma unroll 4
    for (int j = 0; j < Ll / 4; j++) {
        const int l = lq + 4 * j;
        const float tv = t[l];
        const float e1 = __expf((tv - trv) * invk);
        const float e2 = __expf((tlv - tv) * invk);
        const float a  = __fdividef(1.0f, 1.0f + e1) * __fdividef(1.0f, 1.0f + e2);
        sum += a;
        ad[(size_t)l * Mm + m] = make_float2(a, a);
    }
    sum += __shfl_xor_sync(0xFFFFFFFFu, sum, 1);
    sum += __shfl_xor_sync(0xFFFFFFFFu, sum, 2);
    if (lq == 0)
        g_rdenom[n * Mm + m] = 1.0f / (sum + EPSV);
}

// ---------------------------------------------------------------------------
// Kernel 2: out[b,n,m,f] = (sum_l alpha[n,l,m]*x[b,n,l,f]) * rdenom[n,m]
// One CTA per (b-pair, n): grid (16, 32) = 512 CTAs -> single wave at 4 CTA/SM.
// 128 threads; each thread computes a 4(m) x 8(f) micro-tile for BOTH b values
// (alpha smem reused: 6 LDS.128 per 32 FFMA2).
// ---------------------------------------------------------------------------
#define FFMA2(d, a, b) \
    asm("fma.rn.f32x2 %0, %1, %2, %0;" : "+l"(d) : "l"(a), "l"(b))

#define CP_ASYNC16(dst, src) \
    asm volatile("cp.async.cg.shared.global [%0], [%1], 16;" :: "r"(dst), "l"(src))
#define CP_COMMIT() asm volatile("cp.async.commit_group;")
#define CP_WAIT(N)  asm volatile("cp.async.wait_group %0;" :: "n"(N))

typedef unsigned long long ull;

__global__ void __launch_bounds__(128, 4) gemm_kernel(
    const float* __restrict__ x,   // [B,N,L,F]
    float* __restrict__ out)       // [B,N,M,F]
{
    const int bp = blockIdx.x;     // b-pair: b0 = 2*bp, b1 = 2*bp+1
    const int n  = blockIdx.y;

    __shared__ __align__(16) ull   As[2][CHUNK_L * Mm];      // 2 x 8 KB
    __shared__ __align__(16) float Xs[2][2][CHUNK_L * Ff];   // 2 stages x 2 b x 4 KB

    const int tid = threadIdx.x;
    const int m0 = (tid >> 3) * 4;     // 0,4,...,60
    const int f0 = (tid & 7)  * 8;     // 0,8,...,56

    const char* __restrict__ xg0 =
        (const char*)(x + (size_t)(((2 * bp + 0) * Nn + n) * Ll) * Ff);
    const char* __restrict__ xg1 =
        (const char*)(x + (size_t)(((2 * bp + 1) * Nn + n) * Ll) * Ff);
    const char* __restrict__ ag =
        (const char*)(g_alpha_dup + (size_t)(n * Ll) * Mm);

    const unsigned int sA0 = (unsigned int)__cvta_generic_to_shared(&As[0][0]);
    const unsigned int sA1 = (unsigned int)__cvta_generic_to_shared(&As[1][0]);
    const unsigned int sX00 = (unsigned int)__cvta_generic_to_shared(&Xs[0][0][0]);
    const unsigned int sX01 = (unsigned int)__cvta_generic_to_shared(&Xs[0][1][0]);
    const unsigned int sX10 = (unsigned int)__cvta_generic_to_shared(&Xs[1][0][0]);
    const unsigned int sX11 = (unsigned int)__cvta_generic_to_shared(&Xs[1][1][0]);

    // One chunk = 16 l-rows. A: 8192 B (4 x 16B/thread). X: 4096 B per b (2 each).
    auto prefetch = [&](int chunk, int st) {
        const unsigned int dA  = st ? sA1  : sA0;
        const unsigned int dX0 = st ? sX10 : sX00;
        const unsigned int dX1 = st ? sX11 : sX01;
        const char* srcA  = ag  + (size_t)chunk * (CHUNK_L * Mm * 8);
        const char* srcX0 = xg0 + (size_t)chunk * (CHUNK_L * Ff * 4);
        const char* srcX1 = xg1 + (size_t)chunk * (CHUNK_L * Ff * 4);
#pragma unroll
        for (int i = 0; i < 4; i++) {
            const int off = (tid + i * 128) * 16;
            CP_ASYNC16(dA + off, srcA + off);
        }
#pragma unroll
        for (int i = 0; i < 2; i++) {
            const int off = (tid + i * 128) * 16;
            CP_ASYNC16(dX0 + off, srcX0 + off);
        }
#pragma unroll
        for (int i = 0; i < 2; i++) {
            const int off = (tid + i * 128) * 16;
            CP_ASYNC16(dX1 + off, srcX1 + off);
        }
        CP_COMMIT();
    };

    ull acc[2][4][4];
#pragma unroll
    for (int bb = 0; bb < 2; bb++)
#pragma unroll
        for (int i = 0; i < 4; i++)
#pragma unroll
            for (int j = 0; j < 4; j++) acc[bb][i][j] = 0ull;

    prefetch(0, 0);

    for (int chunk = 0; chunk < NCHUNK; chunk++) {
        const int st = chunk & 1;
        if (chunk + 1 < NCHUNK) {
            prefetch(chunk + 1, st ^ 1);
            CP_WAIT(1);            // current chunk's group complete
        } else {
            CP_WAIT(0);
        }
        __syncthreads();

        const ull*   Ab  = &As[st][0];
        const float* Xb0 = &Xs[st][0][0];
        const float* Xb1 = &Xs[st][1][0];
#pragma unroll
        for (int kk = 0; kk < CHUNK_L; kk++) {
            const ulonglong2 a01 = *(const ulonglong2*)(Ab + kk * Mm + m0);
            const ulonglong2 a23 = *(const ulonglong2*)(Ab + kk * Mm + m0 + 2);

            const ulonglong2 p01 = *(const ulonglong2*)(Xb0 + kk * Ff + f0);
            const ulonglong2 p23 = *(const ulonglong2*)(Xb0 + kk * Ff + f0 + 4);
            FFMA2(acc[0][0][0], a01.x, p01.x);
            FFMA2(acc[0][0][1], a01.x, p01.y);
            FFMA2(acc[0][0][2], a01.x, p23.x);
            FFMA2(acc[0][0][3], a01.x, p23.y);
            FFMA2(acc[0][1][0], a01.y, p01.x);
            FFMA2(acc[0][1][1], a01.y, p01.y);
            FFMA2(acc[0][1][2], a01.y, p23.x);
            FFMA2(acc[0][1][3], a01.y, p23.y);
            FFMA2(acc[0][2][0], a23.x, p01.x);
            FFMA2(acc[0][2][1], a23.x, p01.y);
            FFMA2(acc[0][2][2], a23.x, p23.x);
            FFMA2(acc[0][2][3], a23.x, p23.y);
            FFMA2(acc[0][3][0], a23.y, p01.x);
            FFMA2(acc[0][3][1], a23.y, p01.y);
            FFMA2(acc[0][3][2], a23.y, p23.x);
            FFMA2(acc[0][3][3], a23.y, p23.y);

            const ulonglong2 q01 = *(const ulonglong2*)(Xb1 + kk * Ff + f0);
            const ulonglong2 q23 = *(const ulonglong2*)(Xb1 + kk * Ff + f0 + 4);
            FFMA2(acc[1][0][0], a01.x, q01.x);
            FFMA2(acc[1][0][1], a01.x, q01.y);
            FFMA2(acc[1][0][2], a01.x, q23.x);
            FFMA2(acc[1][0][3], a01.x, q23.y);
            FFMA2(acc[1][1][0], a01.y, q01.x);
            FFMA2(acc[1][1][1], a01.y, q01.y);
            FFMA2(acc[1][1][2], a01.y, q23.x);
            FFMA2(acc[1][1][3], a01.y, q23.y);
            FFMA2(acc[1][2][0], a23.x, q01.x);
            FFMA2(acc[1][2][1], a23.x, q01.y);
            FFMA2(acc[1][2][2], a23.x, q23.x);
            FFMA2(acc[1][2][3], a23.x, q23.y);
            FFMA2(acc[1][3][0], a23.y, q01.x);
            FFMA2(acc[1][3][1], a23.y, q01.y);
            FFMA2(acc[1][3][2], a23.y, q23.x);
            FFMA2(acc[1][3][3], a23.y, q23.y);
        }
        __syncthreads();
    }

    // Epilogue: scale by reciprocal denominator; 2 b x 4 m rows x 8 f
#pragma unroll
    for (int bb = 0; bb < 2; bb++) {
        float* __restrict__ og =
            out + (size_t)(((2 * bp + bb) * Nn + n) * Mm) * Ff;
#pragma unroll
        for (int mi = 0; mi < 4; mi++) {
            const float rd = g_rdenom[n * Mm + m0 + mi];
            float4 o0, o1;
            o0.x = __uint_as_float((unsigned int)(acc[bb][mi][0]      )) * rd;
            o0.y = __uint_as_float((unsigned int)(acc[bb][mi][0] >> 32)) * rd;
            o0.z = __uint_as_float((unsigned int)(acc[bb][mi][1]      )) * rd;
            o0.w = __uint_as_float((unsigned int)(acc[bb][mi][1] >> 32)) * rd;
            o1.x = __uint_as_float((unsigned int)(acc[bb][mi][2]      )) * rd;
            o1.y = __uint_as_float((unsigned int)(acc[bb][mi][2] >> 32)) * rd;
            o1.z = __uint_as_float((unsigned int)(acc[bb][mi][3]      )) * rd;
            o1.w = __uint_as_float((unsigned int)(acc[bb][mi][3] >> 32)) * rd;
            *(float4*)&og[(m0 + mi) * Ff + f0]     = o0;
            *(float4*)&og[(m0 + mi) * Ff + f0 + 4] = o1;
        }
    }
}

// ---------------------------------------------------------------------------
// Launch: alpha -> gemm (sequential, graph-capturable)
// Inputs (metadata order): x_aug, t, t_left, t_right, kappa
// ---------------------------------------------------------------------------
extern "C" void kernel_launch(void* const* d_in, const int* in_sizes, int n_in,
                              void* d_out, int out_size)
{
    (void)in_sizes; (void)n_in; (void)out_size;
    const float* x       = (const float*)d_in[0];
    const float* t       = (const float*)d_in[1];
    const float* t_left  = (const float*)d_in[2];
    const float* t_right = (const float*)d_in[3];
    const float* kappa   = (const float*)d_in[4];
    float* out = (float*)d_out;

    alpha_kernel<<<Nn, 256>>>(t, t_left, t_right, kappa);
    gemm_kernel<<<dim3(Bb / 2, Nn), 128>>>(x, out);
}

// round 11
// speedup vs baseline: 1.6345x; 1.6345x over previous
#include <cuda_runtime.h>
#include <cuda_bf16.h>

// Shapes (fixed by problem)
#define Bb 32
#define Nn 32
#define Ll 512
#define Mm 64
#define Ff 64
#define EPSV 1e-8f

#define CHUNK_L 16
#define NCHUNK  (Ll / CHUNK_L)   // 32

// Scratch (no cudaMalloc allowed): alpha scalar f32 [N,L,M] (4 MB)
__device__ float g_alpha[Nn * Ll * Mm];
__device__ float g_rdenom[Nn * Mm];

// ---------------------------------------------------------------------------
// Kernel 1: alpha[n,l,m] = sigmoid((tr-t)/k)*sigmoid((t-tl)/k), k=softplus(kappa)
// + fused denominator. grid 32 (one per n), 256 threads: m=tid&63, ls=tid>>6.
// Warp writes are 128B-contiguous in m.
// ---------------------------------------------------------------------------
__global__ void __launch_bounds__(256) alpha_kernel(
    const float* __restrict__ t,       // [L,1]
    const float* __restrict__ t_left,  // [N,M]
    const float* __restrict__ t_right, // [N,M]
    const float* __restrict__ kappa)   // [N,1]
{
    const int n  = blockIdx.x;
    const int tid = threadIdx.x;
    const int m  = tid & 63;
    const int ls = tid >> 6;   // 0..3

    const float ka = kappa[n];
    const float k  = (ka > 20.0f) ? ka : log1pf(expf(ka));
    const float invk = 1.0f / k;
    const float tlv = t_left [n * Mm + m];
    const float trv = t_right[n * Mm + m];

    float* __restrict__ ad = g_alpha + (size_t)(n * Ll) * Mm;

    float sum = 0.0f;
#pragma unroll 8
    for (int l = ls; l < Ll; l += 4) {
        const float tv = t[l];
        const float e1 = __expf((tv - trv) * invk);
        const float e2 = __expf((tlv - tv) * invk);
        const float a  = __fdividef(1.0f, 1.0f + e1) * __fdividef(1.0f, 1.0f + e2);
        sum += a;
        ad[(size_t)l * Mm + m] = a;
    }
    __shared__ float red[256];
    red[tid] = sum;
    __syncthreads();
    if (ls == 0)
        g_rdenom[n * Mm + m] =
            1.0f / (red[m] + red[m + 64] + red[m + 128] + red[m + 192] + EPSV);
}

// ---------------------------------------------------------------------------
// Kernel 2: out[b,n,m,f] = (sum_l alpha[n,l,m]*x[b,n,l,f]) * rdenom[n,m]
// CTA per (b-pair, n): grid (16, 32). 128 threads = 2 b-halves x (8 mg x 8 fg).
// Each thread: 8(m) x 8(f) micro-tile for ONE b. Alpha smem shared across both
// halves. Inner loop: 4 LDS.128 + 16 MOV(dup) + 32 FFMA2 per kk.
// ---------------------------------------------------------------------------
#define FFMA2(d, a, b) \
    asm("fma.rn.f32x2 %0, %1, %2, %0;" : "+l"(d) : "l"(a), "l"(b))
#define DUP2(d, s) \
    asm("mov.b64 %0, {%1, %1};" : "=l"(d) : "f"(s))

#define CP_ASYNC16(dst, src) \
    asm volatile("cp.async.cg.shared.global [%0], [%1], 16;" :: "r"(dst), "l"(src))
#define CP_COMMIT() asm volatile("cp.async.commit_group;")
#define CP_WAIT(N)  asm volatile("cp.async.wait_group %0;" :: "n"(N))

typedef unsigned long long ull;

__global__ void __launch_bounds__(128, 4) gemm_kernel(
    const float* __restrict__ x,   // [B,N,L,F]
    float* __restrict__ out)       // [B,N,M,F]
{
    const int bp = blockIdx.x;     // b-pair: b = 2*bp + bh
    const int n  = blockIdx.y;

    __shared__ __align__(16) float As[2][CHUNK_L * Mm];      // 2 x 4 KB (scalar)
    __shared__ __align__(16) float Xs[2][2][CHUNK_L * Ff];   // 2 stages x 2 b x 4 KB

    const int tid = threadIdx.x;
    const int bh = tid >> 6;             // which b this thread computes
    const int m0 = ((tid >> 3) & 7) * 8; // 0,8,...,56
    const int f0 = (tid & 7) * 8;        // 0,8,...,56

    const char* __restrict__ xg0 =
        (const char*)(x + (size_t)(((2 * bp + 0) * Nn + n) * Ll) * Ff);
    const char* __restrict__ xg1 =
        (const char*)(x + (size_t)(((2 * bp + 1) * Nn + n) * Ll) * Ff);
    const char* __restrict__ ag =
        (const char*)(g_alpha + (size_t)(n * Ll) * Mm);

    const unsigned int sA0 = (unsigned int)__cvta_generic_to_shared(&As[0][0]);
    const unsigned int sA1 = (unsigned int)__cvta_generic_to_shared(&As[1][0]);
    const unsigned int sX00 = (unsigned int)__cvta_generic_to_shared(&Xs[0][0][0]);
    const unsigned int sX01 = (unsigned int)__cvta_generic_to_shared(&Xs[0][1][0]);
    const unsigned int sX10 = (unsigned int)__cvta_generic_to_shared(&Xs[1][0][0]);
    const unsigned int sX11 = (unsigned int)__cvta_generic_to_shared(&Xs[1][1][0]);

    // One chunk = 16 l-rows. A: 4096 B (2 x 16B/thread). X: 4096 B per b (2 each).
    auto prefetch = [&](int chunk, int st) {
        const unsigned int dA  = st ? sA1  : sA0;
        const unsigned int dX0 = st ? sX10 : sX00;
        const unsigned int dX1 = st ? sX11 : sX01;
        const char* srcA  = ag  + (size_t)chunk * (CHUNK_L * Mm * 4);
        const char* srcX0 = xg0 + (size_t)chunk * (CHUNK_L * Ff * 4);
        const char* srcX1 = xg1 + (size_t)chunk * (CHUNK_L * Ff * 4);
#pragma unroll
        for (int i = 0; i < 2; i++) {
            const int off = (tid + i * 128) * 16;
            CP_ASYNC16(dA + off, srcA + off);
        }
#pragma unroll
        for (int i = 0; i < 2; i++) {
            const int off = (tid + i * 128) * 16;
            CP_ASYNC16(dX0 + off, srcX0 + off);
        }
#pragma unroll
        for (int i = 0; i < 2; i++) {
            const int off = (tid + i * 128) * 16;
            CP_ASYNC16(dX1 + off, srcX1 + off);
        }
        CP_COMMIT();
    };

    ull acc[8][4];
#pragma unroll
    for (int i = 0; i < 8; i++)
#pragma unroll
        for (int j = 0; j < 4; j++) acc[i][j] = 0ull;

    prefetch(0, 0);

    for (int chunk = 0; chunk < NCHUNK; chunk++) {
        const int st = chunk & 1;
        if (chunk + 1 < NCHUNK) {
            prefetch(chunk + 1, st ^ 1);
            CP_WAIT(1);            // current chunk's group complete
        } else {
            CP_WAIT(0);
        }
        __syncthreads();

        const float* Ab = &As[st][0];
        const float* Xb = &Xs[st][bh][0];
#pragma unroll
        for (int kk = 0; kk < CHUNK_L; kk++) {
            const float4 a0 = *(const float4*)(Ab + kk * Mm + m0);
            const float4 a1 = *(const float4*)(Ab + kk * Mm + m0 + 4);
            const ulonglong2 x01 = *(const ulonglong2*)(Xb + kk * Ff + f0);
            const ulonglong2 x23 = *(const ulonglong2*)(Xb + kk * Ff + f0 + 4);

            ull A0, A1, A2, A3, A4, A5, A6, A7;
            DUP2(A0, a0.x); DUP2(A1, a0.y); DUP2(A2, a0.z); DUP2(A3, a0.w);
            DUP2(A4, a1.x); DUP2(A5, a1.y); DUP2(A6, a1.z); DUP2(A7, a1.w);

            FFMA2(acc[0][0], A0, x01.x);
            FFMA2(acc[0][1], A0, x01.y);
            FFMA2(acc[0][2], A0, x23.x);
            FFMA2(acc[0][3], A0, x23.y);
            FFMA2(acc[1][0], A1, x01.x);
            FFMA2(acc[1][1], A1, x01.y);
            FFMA2(acc[1][2], A1, x23.x);
            FFMA2(acc[1][3], A1, x23.y);
            FFMA2(acc[2][0], A2, x01.x);
            FFMA2(acc[2][1], A2, x01.y);
            FFMA2(acc[2][2], A2, x23.x);
            FFMA2(acc[2][3], A2, x23.y);
            FFMA2(acc[3][0], A3, x01.x);
            FFMA2(acc[3][1], A3, x01.y);
            FFMA2(acc[3][2], A3, x23.x);
            FFMA2(acc[3][3], A3, x23.y);
            FFMA2(acc[4][0], A4, x01.x);
            FFMA2(acc[4][1], A4, x01.y);
            FFMA2(acc[4][2], A4, x23.x);
            FFMA2(acc[4][3], A4, x23.y);
            FFMA2(acc[5][0], A5, x01.x);
            FFMA2(acc[5][1], A5, x01.y);
            FFMA2(acc[5][2], A5, x23.x);
            FFMA2(acc[5][3], A5, x23.y);
            FFMA2(acc[6][0], A6, x01.x);
            FFMA2(acc[6][1], A6, x01.y);
            FFMA2(acc[6][2], A6, x23.x);
            FFMA2(acc[6][3], A6, x23.y);
            FFMA2(acc[7][0], A7, x01.x);
            FFMA2(acc[7][1], A7, x01.y);
            FFMA2(acc[7][2], A7, x23.x);
            FFMA2(acc[7][3], A7, x23.y);
        }
        __syncthreads();
    }

    // Epilogue: scale by reciprocal denominator; 8 m rows x 8 f for this b
    float* __restrict__ og =
        out + (size_t)(((2 * bp + bh) * Nn + n) * Mm) * Ff;
#pragma unroll
    for (int mi = 0; mi < 8; mi++) {
        const float rd = g_rdenom[n * Mm + m0 + mi];
        float4 o0, o1;
        o0.x = __uint_as_float((unsigned int)(acc[mi][0]      )) * rd;
        o0.y = __uint_as_float((unsigned int)(acc[mi][0] >> 32)) * rd;
        o0.z = __uint_as_float((unsigned int)(acc[mi][1]      )) * rd;
        o0.w = __uint_as_float((unsigned int)(acc[mi][1] >> 32)) * rd;
        o1.x = __uint_as_float((unsigned int)(acc[mi][2]      )) * rd;
        o1.y = __uint_as_float((unsigned int)(acc[mi][2] >> 32)) * rd;
        o1.z = __uint_as_float((unsigned int)(acc[mi][3]      )) * rd;
        o1.w = __uint_as_float((unsigned int)(acc[mi][3] >> 32)) * rd;
        *(float4*)&og[(m0 + mi) * Ff + f0]     = o0;
        *(float4*)&og[(m0 + mi) * Ff + f0 + 4] = o1;
    }
}

// ---------------------------------------------------------------------------
// Launch: alpha -> gemm (sequential, graph-capturable)
// Inputs (metadata order): x_aug, t, t_left, t_right, kappa
// ---------------------------------------------------------------------------
extern "C" void kernel_launch(void* const* d_in, const int* in_sizes, int n_in,
                              void* d_out, int out_size)
{
    (void)in_sizes; (void)n_in; (void)out_size;
    const float* x       = (const float*)d_in[0];
    const float* t       = (const float*)d_in[1];
    const float* t_left  = (const float*)d_in[2];
    const float* t_right = (const float*)d_in[3];
    const float* kappa   = (const float*)d_in[4];
    float* out = (float*)d_out;

    alpha_kernel<<<Nn, 256>>>(t, t_left, t_right, kappa);
    gemm_kernel<<<dim3(Bb / 2, Nn), 128>>>(x, out);
}

// round 14
// speedup vs baseline: 1.6953x; 1.0372x over previous
#include <cuda_runtime.h>
#include <cuda_bf16.h>

// Shapes (fixed by problem)
#define Bb 32
#define Nn 32
#define Ll 512
#define Mm 64
#define Ff 64
#define EPSV 1e-8f

#define CHUNK_L 16
#define NCHUNK  (Ll / CHUNK_L)   // 32

// Scratch (no cudaMalloc allowed): alpha scalar f32 [N,L,M] (4 MB)
__device__ float g_alpha[Nn * Ll * Mm];
__device__ float g_rdenom[Nn * Mm];

// ---------------------------------------------------------------------------
// Kernel 1: alpha[n,l,m] = sigmoid((tr-t)/k)*sigmoid((t-tl)/k), k=softplus(kappa)
// + fused denominator. grid 32 (one per n), 256 threads.
// ---------------------------------------------------------------------------
__global__ void __launch_bounds__(256) alpha_kernel(
    const float* __restrict__ t,       // [L,1]
    const float* __restrict__ t_left,  // [N,M]
    const float* __restrict__ t_right, // [N,M]
    const float* __restrict__ kappa)   // [N,1]
{
    const int n  = blockIdx.x;
    const int tid = threadIdx.x;
    const int m  = tid & 63;
    const int ls = tid >> 6;   // 0..3

    const float ka = kappa[n];
    const float k  = (ka > 20.0f) ? ka : log1pf(expf(ka));
    const float invk = 1.0f / k;
    const float tlv = t_left [n * Mm + m];
    const float trv = t_right[n * Mm + m];

    float* __restrict__ ad = g_alpha + (size_t)(n * Ll) * Mm;

    float sum = 0.0f;
#pragma unroll 8
    for (int l = ls; l < Ll; l += 4) {
        const float tv = t[l];
        const float e1 = __expf((tv - trv) * invk);
        const float e2 = __expf((tlv - tv) * invk);
        const float a  = __fdividef(1.0f, 1.0f + e1) * __fdividef(1.0f, 1.0f + e2);
        sum += a;
        ad[(size_t)l * Mm + m] = a;
    }
    __shared__ float red[256];
    red[tid] = sum;
    __syncthreads();
    if (ls == 0)
        g_rdenom[n * Mm + m] =
            1.0f / (red[m] + red[m + 64] + red[m + 128] + red[m + 192] + EPSV);
}

// ---------------------------------------------------------------------------
// Kernel 2: out[b,n,m,f] = (sum_l alpha[n,l,m]*x[b,n,l,f]) * rdenom[n,m]
// CTA per (b-pair, n): grid (16, 32), 64 threads.
// Warp 0 computes b0, warp 1 computes b1 (alpha smem shared).
// Each thread: 8(m) x 16(f) micro-tile. Inner loop per kk:
//   6 LDS.128 + 8 DUP + 64 FFMA2  (LDS:FFMA2 ratio 0.094).
// ---------------------------------------------------------------------------
#define FFMA2(d, a, b) \
    asm("fma.rn.f32x2 %0, %1, %2, %0;" : "+l"(d) : "l"(a), "l"(b))
#define DUP2(d, s) \
    asm("mov.b64 %0, {%1, %1};" : "=l"(d) : "f"(s))

#define CP_ASYNC16(dst, src) \
    asm volatile("cp.async.cg.shared.global [%0], [%1], 16;" :: "r"(dst), "l"(src))
#define CP_COMMIT() asm volatile("cp.async.commit_group;")
#define CP_WAIT(N)  asm volatile("cp.async.wait_group %0;" :: "n"(N))

typedef unsigned long long ull;

__global__ void __launch_bounds__(64) gemm_kernel(
    const float* __restrict__ x,   // [B,N,L,F]
    float* __restrict__ out)       // [B,N,M,F]
{
    const int bp = blockIdx.x;     // b-pair: b = 2*bp + bh
    const int n  = blockIdx.y;

    __shared__ __align__(16) float As[2][CHUNK_L * Mm];      // 2 x 4 KB (scalar)
    __shared__ __align__(16) float Xs[2][2][CHUNK_L * Ff];   // 2 stages x 2 b x 4 KB

    const int tid = threadIdx.x;
    const int bh = tid >> 5;             // warp -> which b
    const int m0 = ((tid >> 2) & 7) * 8; // 0,8,...,56
    const int f0 = (tid & 3) * 16;       // 0,16,32,48

    const char* __restrict__ xg0 =
        (const char*)(x + (size_t)(((2 * bp + 0) * Nn + n) * Ll) * Ff);
    const char* __restrict__ xg1 =
        (const char*)(x + (size_t)(((2 * bp + 1) * Nn + n) * Ll) * Ff);
    const char* __restrict__ ag =
        (const char*)(g_alpha + (size_t)(n * Ll) * Mm);

    const unsigned int sA0 = (unsigned int)__cvta_generic_to_shared(&As[0][0]);
    const unsigned int sA1 = (unsigned int)__cvta_generic_to_shared(&As[1][0]);
    const unsigned int sX00 = (unsigned int)__cvta_generic_to_shared(&Xs[0][0][0]);
    const unsigned int sX01 = (unsigned int)__cvta_generic_to_shared(&Xs[0][1][0]);
    const unsigned int sX10 = (unsigned int)__cvta_generic_to_shared(&Xs[1][0][0]);
    const unsigned int sX11 = (unsigned int)__cvta_generic_to_shared(&Xs[1][1][0]);

    // One chunk = 16 l-rows. A: 4096 B, X: 4096 B per b. 64 thr x 16B x 4 iters.
    auto prefetch = [&](int chunk, int st) {
        const unsigned int dA  = st ? sA1  : sA0;
        const unsigned int dX0 = st ? sX10 : sX00;
        const unsigned int dX1 = st ? sX11 : sX01;
        const char* srcA  = ag  + (size_t)chunk * (CHUNK_L * Mm * 4);
        const char* srcX0 = xg0 + (size_t)chunk * (CHUNK_L * Ff * 4);
        const char* srcX1 = xg1 + (size_t)chunk * (CHUNK_L * Ff * 4);
#pragma unroll
        for (int i = 0; i < 4; i++) {
            const int off = (tid + i * 64) * 16;
            CP_ASYNC16(dA + off, srcA + off);
        }
#pragma unroll
        for (int i = 0; i < 4; i++) {
            const int off = (tid + i * 64) * 16;
            CP_ASYNC16(dX0 + off, srcX0 + off);
        }
#pragma unroll
        for (int i = 0; i < 4; i++) {
            const int off = (tid + i * 64) * 16;
            CP_ASYNC16(dX1 + off, srcX1 + off);
        }
        CP_COMMIT();
    };

    ull acc[8][8];
#pragma unroll
    for (int i = 0; i < 8; i++)
#pragma unroll
        for (int j = 0; j < 8; j++) acc[i][j] = 0ull;

    prefetch(0, 0);

    for (int chunk = 0; chunk < NCHUNK; chunk++) {
        const int st = chunk & 1;
        if (chunk + 1 < NCHUNK) {
            prefetch(chunk + 1, st ^ 1);
            CP_WAIT(1);            // current chunk's group complete
        } else {
            CP_WAIT(0);
        }
        __syncthreads();

        const float* Ab = &As[st][0];
        const float* Xb = &Xs[st][bh][0];
#pragma unroll
        for (int kk = 0; kk < CHUNK_L; kk++) {
            const float4 a0 = *(const float4*)(Ab + kk * Mm + m0);
            const float4 a1 = *(const float4*)(Ab + kk * Mm + m0 + 4);
            ull A[8];
            DUP2(A[0], a0.x); DUP2(A[1], a0.y); DUP2(A[2], a0.z); DUP2(A[3], a0.w);
            DUP2(A[4], a1.x); DUP2(A[5], a1.y); DUP2(A[6], a1.z); DUP2(A[7], a1.w);

            ull xv[8];
            {
                const ulonglong2 v0 = *(const ulonglong2*)(Xb + kk * Ff + f0);
                const ulonglong2 v1 = *(const ulonglong2*)(Xb + kk * Ff + f0 + 4);
                const ulonglong2 v2 = *(const ulonglong2*)(Xb + kk * Ff + f0 + 8);
                const ulonglong2 v3 = *(const ulonglong2*)(Xb + kk * Ff + f0 + 12);
                xv[0] = v0.x; xv[1] = v0.y; xv[2] = v1.x; xv[3] = v1.y;
                xv[4] = v2.x; xv[5] = v2.y; xv[6] = v3.x; xv[7] = v3.y;
            }
#pragma unroll
            for (int mi = 0; mi < 8; mi++) {
#pragma unroll
                for (int fj = 0; fj < 8; fj++)
                    FFMA2(acc[mi][fj], A[mi], xv[fj]);
            }
        }
        __syncthreads();
    }

    // Epilogue: scale by reciprocal denominator; 8 m rows x 16 f for this b
    float* __restrict__ og =
        out + (size_t)(((2 * bp + bh) * Nn + n) * Mm) * Ff;
#pragma unroll
    for (int mi = 0; mi < 8; mi++) {
        const float rd = g_rdenom[n * Mm + m0 + mi];
#pragma unroll
        for (int q = 0; q < 4; q++) {
            float4 o;
            o.x = __uint_as_float((unsigned int)(acc[mi][2 * q]      )) * rd;
            o.y = __uint_as_float((unsigned int)(acc[mi][2 * q] >> 32)) * rd;
            o.z = __uint_as_float((unsigned int)(acc[mi][2 * q + 1]      )) * rd;
            o.w = __uint_as_float((unsigned int)(acc[mi][2 * q + 1] >> 32)) * rd;
            *(float4*)&og[(m0 + mi) * Ff + f0 + 4 * q] = o;
        }
    }
}

// ---------------------------------------------------------------------------
// Launch: alpha -> gemm (sequential, graph-capturable)
// Inputs (metadata order): x_aug, t, t_left, t_right, kappa
// ---------------------------------------------------------------------------
extern "C" void kernel_launch(void* const* d_in, const int* in_sizes, int n_in,
                              void* d_out, int out_size)
{
    (void)in_sizes; (void)n_in; (void)out_size;
    const float* x       = (const float*)d_in[0];
    const float* t       = (const float*)d_in[1];
    const float* t_left  = (const float*)d_in[2];
    const float* t_right = (const float*)d_in[3];
    const float* kappa   = (const float*)d_in[4];
    float* out = (float*)d_out;

    alpha_kernel<<<Nn, 256>>>(t, t_left, t_right, kappa);
    gemm_kernel<<<dim3(Bb / 2, Nn), 64>>>(x, out);
}

// round 15
// speedup vs baseline: 2.3552x; 1.3892x over previous
#include <cuda_runtime.h>
#include <cuda_bf16.h>

// Shapes (fixed by problem)
#define Bb 32
#define Nn 32
#define Ll 512
#define Mm 64
#define Ff 64
#define EPSV 1e-8f

#define CHUNK_L 16
#define NCHUNK  (Ll / CHUNK_L)   // 32
#define PITCH   144              // smem row pitch (128B data + 16B pad)

// Scratch (no cudaMalloc): alpha split hi/lo bf16 [N,L,M] (2 MB each)
__device__ __nv_bfloat16 g_Ah[Nn * Ll * Mm];
__device__ __nv_bfloat16 g_Al[Nn * Ll * Mm];
__device__ float g_rdenom[Nn * Mm];

// ---------------------------------------------------------------------------
// PTX helpers
// ---------------------------------------------------------------------------
__device__ __forceinline__ unsigned int cvt2bf(float a, float b) {
    // packed: low half = bf16(a), high half = bf16(b)
    unsigned int r;
    asm("cvt.rn.bf16x2.f32 %0, %1, %2;" : "=r"(r) : "f"(b), "f"(a));
    return r;
}

#define CP_ASYNC16(dst, src) \
    asm volatile("cp.async.cg.shared.global [%0], [%1], 16;" :: "r"(dst), "l"(src))
#define CP_COMMIT() asm volatile("cp.async.commit_group;")
#define CP_WAIT(N)  asm volatile("cp.async.wait_group %0;" :: "n"(N))

#define STS128(a0, a1, a2, a3, addr) \
    asm volatile("st.shared.v4.b32 [%0], {%1, %2, %3, %4};" \
                 :: "r"(addr), "r"(a0), "r"(a1), "r"(a2), "r"(a3) : "memory")

#define LDSM4T(r0, r1, r2, r3, addr) \
    asm volatile("ldmatrix.sync.aligned.m8n8.x4.trans.shared.b16 {%0,%1,%2,%3}, [%4];" \
                 : "=r"(r0), "=r"(r1), "=r"(r2), "=r"(r3) : "r"(addr))

#define MMA16816(d, a, b0, b1) \
    asm volatile("mma.sync.aligned.m16n8k16.row.col.f32.bf16.bf16.f32 " \
                 "{%0,%1,%2,%3}, {%4,%5,%6,%7}, {%8,%9}, {%0,%1,%2,%3};" \
                 : "+f"((d)[0]), "+f"((d)[1]), "+f"((d)[2]), "+f"((d)[3]) \
                 : "r"((a)[0]), "r"((a)[1]), "r"((a)[2]), "r"((a)[3]), \
                   "r"(b0), "r"(b1))

// ---------------------------------------------------------------------------
// Kernel 1: alpha + bf16 hi/lo split + fused denominator.
// grid 32 (one per n), 256 threads.
// ---------------------------------------------------------------------------
__global__ void __launch_bounds__(256) alpha_kernel(
    const float* __restrict__ t,       // [L,1]
    const float* __restrict__ t_left,  // [N,M]
    const float* __restrict__ t_right, // [N,M]
    const float* __restrict__ kappa)   // [N,1]
{
    const int n  = blockIdx.x;
    const int tid = threadIdx.x;
    const int m  = tid & 63;
    const int ls = tid >> 6;   // 0..3

    const float ka = kappa[n];
    const float k  = (ka > 20.0f) ? ka : log1pf(expf(ka));
    const float invk = 1.0f / k;
    const float tlv = t_left [n * Mm + m];
    const float trv = t_right[n * Mm + m];

    __nv_bfloat16* __restrict__ ah = g_Ah + (size_t)(n * Ll) * Mm;
    __nv_bfloat16* __restrict__ al = g_Al + (size_t)(n * Ll) * Mm;

    float sum = 0.0f;
#pragma unroll 8
    for (int l = ls; l < Ll; l += 4) {
        const float tv = t[l];
        const float e1 = __expf((tv - trv) * invk);
        const float e2 = __expf((tlv - tv) * invk);
        const float a  = __fdividef(1.0f, 1.0f + e1) * __fdividef(1.0f, 1.0f + e2);
        sum += a;
        const __nv_bfloat16 hb = __float2bfloat16(a);
        const float hf = __bfloat162float(hb);
        ah[(size_t)l * Mm + m] = hb;
        al[(size_t)l * Mm + m] = __float2bfloat16(a - hf);
    }
    __shared__ float red[256];
    red[tid] = sum;
    __syncthreads();
    if (ls == 0)
        g_rdenom[n * Mm + m] =
            1.0f / (red[m] + red[m + 64] + red[m + 128] + red[m + 192] + EPSV);
}

// ---------------------------------------------------------------------------
// Kernel 2: mma.sync bf16 3-term split GEMM.
// CTA per (b-pair, n): grid (16, 32), 128 threads / 4 warps.
// Warp w computes m-rows [16w, 16w+16) x f[0,64) for BOTH b of the pair
// (A fragments shared). D += Ahi*Xhi + Alo*Xhi + Ahi*Xlo, fp32 accum.
// ---------------------------------------------------------------------------
__global__ void __launch_bounds__(128) gemm_kernel(
    const float* __restrict__ x,   // [B,N,L,F]
    float* __restrict__ out)       // [B,N,M,F]
{
    const int bp = blockIdx.x;
    const int n  = blockIdx.y;
    const int tid = threadIdx.x;
    const int lane = tid & 31;
    const int w = tid >> 5;        // warp 0..3 -> m-slice
    const int m0 = w * 16;

    __shared__ __align__(16) unsigned char Ah_s[2][CHUNK_L * PITCH];
    __shared__ __align__(16) unsigned char Al_s[2][CHUNK_L * PITCH];
    __shared__ __align__(16) unsigned char X_s[2][2][2][CHUNK_L * PITCH]; // [st][b][hi/lo]

    const char* __restrict__ xg[2] = {
        (const char*)(x + (size_t)(((2 * bp + 0) * Nn + n) * Ll) * Ff),
        (const char*)(x + (size_t)(((2 * bp + 1) * Nn + n) * Ll) * Ff) };
    const char* __restrict__ agH = (const char*)(g_Ah + (size_t)(n * Ll) * Mm);
    const char* __restrict__ agL = (const char*)(g_Al + (size_t)(n * Ll) * Mm);

    unsigned int sAh[2], sAl[2], sX[2][2][2];
#pragma unroll
    for (int s = 0; s < 2; s++) {
        sAh[s] = (unsigned int)__cvta_generic_to_shared(&Ah_s[s][0]);
        sAl[s] = (unsigned int)__cvta_generic_to_shared(&Al_s[s][0]);
#pragma unroll
        for (int b = 0; b < 2; b++)
#pragma unroll
            for (int h = 0; h < 2; h++)
                sX[s][b][h] = (unsigned int)__cvta_generic_to_shared(&X_s[s][b][h][0]);
    }

    // cp.async A roles: 128 threads x 16B covers one 16x64 bf16 tile (2 KB)
    const int arow = tid >> 3, aseg = tid & 7;
    // x conversion roles: 64 threads per b, each 16 f32 of one l-row
    const int bh_t = tid >> 6;
    const int jj = tid & 63;
    const int lrow = jj >> 2;
    const int xf0 = (jj & 3) * 16;

    auto prefetchA = [&](int chunk, int st) {
        const size_t off = ((size_t)(chunk * CHUNK_L + arow) * Mm + aseg * 8) * 2;
        const unsigned int d = arow * PITCH + aseg * 16;
        CP_ASYNC16(sAh[st] + d, agH + off);
        CP_ASYNC16(sAl[st] + d, agL + off);
        CP_COMMIT();
    };

    // ldmatrix per-lane element offsets (bytes, within a tile)
    // A (from [k][m], .trans): matrices (m0-7,k0-7),(m8-15,k0-7),(m0-7,k8-15),(m8-15,k8-15)
    const unsigned int aoff =
        ((lane & 7) + ((lane >> 4) & 1) * 8) * PITCH + m0 * 2 + ((lane >> 3) & 1) * 16;
    // B (from [k][f], .trans): per n16 group g: b0(g0),b1(g0),b0(g0+8),b1(g0+8)
    const unsigned int boff =
        ((lane & 7) + ((lane >> 3) & 1) * 8) * PITCH + (lane >> 4) * 16;

    float acc[2][8][4];
#pragma unroll
    for (int b = 0; b < 2; b++)
#pragma unroll
        for (int t = 0; t < 8; t++)
#pragma unroll
            for (int i = 0; i < 4; i++) acc[b][t][i] = 0.0f;

    float4 xr[4];
#pragma unroll
    for (int q = 0; q < 4; q++)
        xr[q] = *(const float4*)(xg[bh_t] + ((size_t)lrow * Ff + xf0 + 4 * q) * 4);

    prefetchA(0, 0);

    for (int c = 0; c < NCHUNK; c++) {
        const int s = c & 1;
        if (c + 1 < NCHUNK) {
            prefetchA(c + 1, s ^ 1);
            CP_WAIT(1);
        } else {
            CP_WAIT(0);
        }

        // convert this chunk's x regs -> bf16 hi/lo smem tiles
        {
            unsigned int hi[8], lo[8];
#pragma unroll
            for (int q = 0; q < 4; q++) {
                const float4 v = xr[q];
                const unsigned int h0 = cvt2bf(v.x, v.y);
                const unsigned int h1 = cvt2bf(v.z, v.w);
                hi[2 * q]     = h0;
                hi[2 * q + 1] = h1;
                lo[2 * q]     = cvt2bf(v.x - __uint_as_float(h0 << 16),
                                       v.y - __uint_as_float(h0 & 0xFFFF0000u));
                lo[2 * q + 1] = cvt2bf(v.z - __uint_as_float(h1 << 16),
                                       v.w - __uint_as_float(h1 & 0xFFFF0000u));
            }
            const unsigned int dH = sX[s][bh_t][0] + lrow * PITCH + xf0 * 2;
            const unsigned int dL = sX[s][bh_t][1] + lrow * PITCH + xf0 * 2;
            STS128(hi[0], hi[1], hi[2], hi[3], dH);
            STS128(hi[4], hi[5], hi[6], hi[7], dH + 16);
            STS128(lo[0], lo[1], lo[2], lo[3], dL);
            STS128(lo[4], lo[5], lo[6], lo[7], dL + 16);
        }
        // prefetch next chunk's x into regs (overlaps MMA)
        if (c + 1 < NCHUNK) {
#pragma unroll
            for (int q = 0; q < 4; q++)
                xr[q] = *(const float4*)(xg[bh_t] +
                    ((size_t)((c + 1) * CHUNK_L + lrow) * Ff + xf0 + 4 * q) * 4);
        }
        __syncthreads();

        // compute on stage s
        unsigned int ah[4], al[4];
        LDSM4T(ah[0], ah[1], ah[2], ah[3], sAh[s] + aoff);
        LDSM4T(al[0], al[1], al[2], al[3], sAl[s] + aoff);
#pragma unroll
        for (int b = 0; b < 2; b++) {
#pragma unroll
            for (int g = 0; g < 4; g++) {
                unsigned int bh[4], bl[4];
                LDSM4T(bh[0], bh[1], bh[2], bh[3], sX[s][b][0] + boff + 32 * g);
                LDSM4T(bl[0], bl[1], bl[2], bl[3], sX[s][b][1] + boff + 32 * g);
                MMA16816(acc[b][2 * g],     ah, bh[0], bh[1]);
                MMA16816(acc[b][2 * g],     al, bh[0], bh[1]);
                MMA16816(acc[b][2 * g],     ah, bl[0], bl[1]);
                MMA16816(acc[b][2 * g + 1], ah, bh[2], bh[3]);
                MMA16816(acc[b][2 * g + 1], al, bh[2], bh[3]);
                MMA16816(acc[b][2 * g + 1], ah, bl[2], bl[3]);
            }
        }
        __syncthreads();
    }

    // Epilogue: D frag (m16n8): d0,d1 -> (row, c0/c0+1); d2,d3 -> (row+8, ...)
    const int row = lane >> 2;
    const int c0  = (lane & 3) * 2;
    const float rd0 = g_rdenom[n * Mm + m0 + row];
    const float rd1 = g_rdenom[n * Mm + m0 + row + 8];
#pragma unroll
    for (int b = 0; b < 2; b++) {
        float* __restrict__ og =
            out + (size_t)(((2 * bp + b) * Nn + n) * Mm) * Ff;
#pragma unroll
        for (int t = 0; t < 8; t++) {
            const int f = 8 * t + c0;
            float2 p0, p1;
            p0.x = acc[b][t][0] * rd0;
            p0.y = acc[b][t][1] * rd0;
            p1.x = acc[b][t][2] * rd1;
            p1.y = acc[b][t][3] * rd1;
            *(float2*)&og[(m0 + row) * Ff + f]     = p0;
            *(float2*)&og[(m0 + row + 8) * Ff + f] = p1;
        }
    }
}

// ---------------------------------------------------------------------------
// Launch: alpha -> gemm (sequential, graph-capturable)
// Inputs (metadata order): x_aug, t, t_left, t_right, kappa
// ---------------------------------------------------------------------------
extern "C" void kernel_launch(void* const* d_in, const int* in_sizes, int n_in,
                              void* d_out, int out_size)
{
    (void)in_sizes; (void)n_in; (void)out_size;
    const float* x       = (const float*)d_in[0];
    const float* t       = (const float*)d_in[1];
    const float* t_left  = (const float*)d_in[2];
    const float* t_right = (const float*)d_in[3];
    const float* kappa   = (const float*)d_in[4];
    float* out = (float*)d_out;

    alpha_kernel<<<Nn, 256>>>(t, t_left, t_right, kappa);
    gemm_kernel<<<dim3(Bb / 2, Nn), 128>>>(x, out);
}

// round 16
// speedup vs baseline: 2.6383x; 1.1202x over previous
#include <cuda_runtime.h>
#include <cuda_bf16.h>

// Shapes (fixed by problem)
#define Bb 32
#define Nn 32
#define Ll 512
#define Mm 64
#define Ff 64
#define EPSV 1e-8f

#define CHUNK_L 16
#define NCHUNK  (Ll / CHUNK_L)   // 32
#define PITCH   144              // smem row pitch (128B data + 16B pad)

// Scratch (no cudaMalloc): alpha split hi/lo bf16 [N,L,M] (2 MB each)
__device__ __nv_bfloat16 g_Ah[Nn * Ll * Mm];
__device__ __nv_bfloat16 g_Al[Nn * Ll * Mm];
__device__ float g_rdenom[Nn * Mm];

// ---------------------------------------------------------------------------
// PTX helpers
// ---------------------------------------------------------------------------
__device__ __forceinline__ unsigned int cvt2bf(float a, float b) {
    // packed: low half = bf16(a), high half = bf16(b)
    unsigned int r;
    asm("cvt.rn.bf16x2.f32 %0, %1, %2;" : "=r"(r) : "f"(b), "f"(a));
    return r;
}

#define CP_ASYNC16(dst, src) \
    asm volatile("cp.async.cg.shared.global [%0], [%1], 16;" :: "r"(dst), "l"(src))
#define CP_COMMIT() asm volatile("cp.async.commit_group;")
#define CP_WAIT(N)  asm volatile("cp.async.wait_group %0;" :: "n"(N))

#define STS128(a0, a1, a2, a3, addr) \
    asm volatile("st.shared.v4.b32 [%0], {%1, %2, %3, %4};" \
                 :: "r"(addr), "r"(a0), "r"(a1), "r"(a2), "r"(a3) : "memory")

#define LDSM4T(r0, r1, r2, r3, addr) \
    asm volatile("ldmatrix.sync.aligned.m8n8.x4.trans.shared.b16 {%0,%1,%2,%3}, [%4];" \
                 : "=r"(r0), "=r"(r1), "=r"(r2), "=r"(r3) : "r"(addr))

#define MMA16816(d, a, b0, b1) \
    asm volatile("mma.sync.aligned.m16n8k16.row.col.f32.bf16.bf16.f32 " \
                 "{%0,%1,%2,%3}, {%4,%5,%6,%7}, {%8,%9}, {%0,%1,%2,%3};" \
                 : "+f"((d)[0]), "+f"((d)[1]), "+f"((d)[2]), "+f"((d)[3]) \
                 : "r"((a)[0]), "r"((a)[1]), "r"((a)[2]), "r"((a)[3]), \
                   "r"(b0), "r"(b1))

// ---------------------------------------------------------------------------
// Kernel 1: alpha + bf16 hi/lo split. grid (8, 32) x 256 threads.
// ---------------------------------------------------------------------------
__global__ void __launch_bounds__(256) alpha_kernel(
    const float* __restrict__ t,       // [L,1]
    const float* __restrict__ t_left,  // [N,M]
    const float* __restrict__ t_right, // [N,M]
    const float* __restrict__ kappa)   // [N,1]
{
    const int n  = blockIdx.y;
    const int l0 = blockIdx.x * 64;
    const int tid = threadIdx.x;
    const int m  = tid & 63;
    const int ls = tid >> 6;   // 0..3

    const float ka = kappa[n];
    const float k  = (ka > 20.0f) ? ka : log1pf(expf(ka));
    const float invk = 1.0f / k;
    const float tlv = t_left [n * Mm + m];
    const float trv = t_right[n * Mm + m];

    __nv_bfloat16* __restrict__ ah = g_Ah + (size_t)(n * Ll) * Mm;
    __nv_bfloat16* __restrict__ al = g_Al + (size_t)(n * Ll) * Mm;

#pragma unroll
    for (int j = 0; j < 16; j++) {
        const int l = l0 + ls + 4 * j;
        const float tv = t[l];
        const float e1 = __expf((tv - trv) * invk);
        const float e2 = __expf((tlv - tv) * invk);
        const float a  = __fdividef(1.0f, 1.0f + e1) * __fdividef(1.0f, 1.0f + e2);
        const __nv_bfloat16 hb = __float2bfloat16(a);
        const float hf = __bfloat162float(hb);
        ah[(size_t)l * Mm + m] = hb;
        al[(size_t)l * Mm + m] = __float2bfloat16(a - hf);
    }
}

// ---------------------------------------------------------------------------
// Kernel 2: rdenom[n,m] = 1/(sum_l (hi+lo) + EPS). grid 32 x 256 threads.
// hi+lo reproduces alpha to ~2^-18 relative — far below the 1e-3 tolerance.
// ---------------------------------------------------------------------------
__global__ void __launch_bounds__(256) denom_kernel()
{
    const int n = blockIdx.x;
    const int tid = threadIdx.x;
    const int m  = tid & 63;
    const int ls = tid >> 6;

    const __nv_bfloat16* __restrict__ ah = g_Ah + (size_t)(n * Ll) * Mm;
    const __nv_bfloat16* __restrict__ al = g_Al + (size_t)(n * Ll) * Mm;

    float s = 0.0f;
#pragma unroll 8
    for (int l = ls; l < Ll; l += 4)
        s += __bfloat162float(ah[(size_t)l * Mm + m]) +
             __bfloat162float(al[(size_t)l * Mm + m]);

    __shared__ float red[256];
    red[tid] = s;
    __syncthreads();
    if (ls == 0)
        g_rdenom[n * Mm + m] =
            1.0f / (red[m] + red[m + 64] + red[m + 128] + red[m + 192] + EPSV);
}

// ---------------------------------------------------------------------------
// Kernel 3: mma.sync bf16 3-term split GEMM.
// CTA per (b-pair, n): grid (16, 32), 128 threads / 4 warps.
// Warp w owns f-slice [16w, 16w+16), ALL 64 m, BOTH b of the pair.
// Per warp-chunk: 12 LDSM.x4 (8 A + 4 B) + 48 MMA.
// D += Ahi*Xhi + Alo*Xhi + Ahi*Xlo, fp32 accum.
// ---------------------------------------------------------------------------
__global__ void __launch_bounds__(128) gemm_kernel(
    const float* __restrict__ x,   // [B,N,L,F]
    float* __restrict__ out)       // [B,N,M,F]
{
    const int bp = blockIdx.x;
    const int n  = blockIdx.y;
    const int tid = threadIdx.x;
    const int lane = tid & 31;
    const int w = tid >> 5;        // warp 0..3 -> f-slice 16w

    __shared__ __align__(16) unsigned char Ah_s[2][CHUNK_L * PITCH];
    __shared__ __align__(16) unsigned char Al_s[2][CHUNK_L * PITCH];
    __shared__ __align__(16) unsigned char X_s[2][2][2][CHUNK_L * PITCH]; // [st][b][hi/lo]

    const char* __restrict__ xg[2] = {
        (const char*)(x + (size_t)(((2 * bp + 0) * Nn + n) * Ll) * Ff),
        (const char*)(x + (size_t)(((2 * bp + 1) * Nn + n) * Ll) * Ff) };
    const char* __restrict__ agH = (const char*)(g_Ah + (size_t)(n * Ll) * Mm);
    const char* __restrict__ agL = (const char*)(g_Al + (size_t)(n * Ll) * Mm);

    unsigned int sAh[2], sAl[2], sX[2][2][2];
#pragma unroll
    for (int s = 0; s < 2; s++) {
        sAh[s] = (unsigned int)__cvta_generic_to_shared(&Ah_s[s][0]);
        sAl[s] = (unsigned int)__cvta_generic_to_shared(&Al_s[s][0]);
#pragma unroll
        for (int b = 0; b < 2; b++)
#pragma unroll
            for (int h = 0; h < 2; h++)
                sX[s][b][h] = (unsigned int)__cvta_generic_to_shared(&X_s[s][b][h][0]);
    }

    // cp.async A roles: 128 threads x 16B covers one 16x64 bf16 tile (2 KB)
    const int arow = tid >> 3, aseg = tid & 7;
    // x conversion roles: 64 threads per b, each 16 f32 of one l-row
    const int bh_t = tid >> 6;
    const int jj = tid & 63;
    const int lrow = jj >> 2;
    const int xf0 = (jj & 3) * 16;

    auto prefetchA = [&](int chunk, int st) {
        const size_t off = ((size_t)(chunk * CHUNK_L + arow) * Mm + aseg * 8) * 2;
        const unsigned int d = arow * PITCH + aseg * 16;
        CP_ASYNC16(sAh[st] + d, agH + off);
        CP_ASYNC16(sAl[st] + d, agL + off);
        CP_COMMIT();
    };

    // ldmatrix per-lane byte offsets (validated in R15)
    // A tile [k16][m64]: frag g (m = 16g..16g+15) at aoffb + 32*g
    const unsigned int aoffb =
        ((lane & 7) + ((lane >> 4) & 1) * 8) * PITCH + ((lane >> 3) & 1) * 16;
    // B tile [k16][f64]: this warp's f-slice at boffw
    const unsigned int boffw =
        ((lane & 7) + ((lane >> 3) & 1) * 8) * PITCH + (lane >> 4) * 16 + 32 * w;

    float acc[2][4][2][4];   // [b][m-tile g][n8 j][frag]
#pragma unroll
    for (int b = 0; b < 2; b++)
#pragma unroll
        for (int g = 0; g < 4; g++)
#pragma unroll
            for (int j = 0; j < 2; j++)
#pragma unroll
                for (int i = 0; i < 4; i++) acc[b][g][j][i] = 0.0f;

    float4 xr[4];
#pragma unroll
    for (int q = 0; q < 4; q++)
        xr[q] = *(const float4*)(xg[bh_t] + ((size_t)lrow * Ff + xf0 + 4 * q) * 4);

    prefetchA(0, 0);

    for (int c = 0; c < NCHUNK; c++) {
        const int s = c & 1;
        if (c + 1 < NCHUNK) {
            prefetchA(c + 1, s ^ 1);
            CP_WAIT(1);
        } else {
            CP_WAIT(0);
        }

        // convert this chunk's x regs -> bf16 hi/lo smem tiles
        {
            unsigned int hi[8], lo[8];
#pragma unroll
            for (int q = 0; q < 4; q++) {
                const float4 v = xr[q];
                const unsigned int h0 = cvt2bf(v.x, v.y);
                const unsigned int h1 = cvt2bf(v.z, v.w);
                hi[2 * q]     = h0;
                hi[2 * q + 1] = h1;
                lo[2 * q]     = cvt2bf(v.x - __uint_as_float(h0 << 16),
                                       v.y - __uint_as_float(h0 & 0xFFFF0000u));
                lo[2 * q + 1] = cvt2bf(v.z - __uint_as_float(h1 << 16),
                                       v.w - __uint_as_float(h1 & 0xFFFF0000u));
            }
            const unsigned int dH = sX[s][bh_t][0] + lrow * PITCH + xf0 * 2;
            const unsigned int dL = sX[s][bh_t][1] + lrow * PITCH + xf0 * 2;
            STS128(hi[0], hi[1], hi[2], hi[3], dH);
            STS128(hi[4], hi[5], hi[6], hi[7], dH + 16);
            STS128(lo[0], lo[1], lo[2], lo[3], dL);
            STS128(lo[4], lo[5], lo[6], lo[7], dL + 16);
        }
        // prefetch next chunk's x into regs (overlaps MMA)
        if (c + 1 < NCHUNK) {
#pragma unroll
            for (int q = 0; q < 4; q++)
                xr[q] = *(const float4*)(xg[bh_t] +
                    ((size_t)((c + 1) * CHUNK_L + lrow) * Ff + xf0 + 4 * q) * 4);
        }
        __syncthreads();

        // compute on stage s: load all A frags once, B frags for this f-slice
        unsigned int ah[4][4], al[4][4];
#pragma unroll
        for (int g = 0; g < 4; g++) {
            LDSM4T(ah[g][0], ah[g][1], ah[g][2], ah[g][3], sAh[s] + aoffb + 32 * g);
            LDSM4T(al[g][0], al[g][1], al[g][2], al[g][3], sAl[s] + aoffb + 32 * g);
        }
#pragma unroll
        for (int b = 0; b < 2; b++) {
            unsigned int bh[4], bl[4];
            LDSM4T(bh[0], bh[1], bh[2], bh[3], sX[s][b][0] + boffw);
            LDSM4T(bl[0], bl[1], bl[2], bl[3], sX[s][b][1] + boffw);
#pragma unroll
            for (int g = 0; g < 4; g++) {
                MMA16816(acc[b][g][0], ah[g], bh[0], bh[1]);
                MMA16816(acc[b][g][0], al[g], bh[0], bh[1]);
                MMA16816(acc[b][g][0], ah[g], bl[0], bl[1]);
                MMA16816(acc[b][g][1], ah[g], bh[2], bh[3]);
                MMA16816(acc[b][g][1], al[g], bh[2], bh[3]);
                MMA16816(acc[b][g][1], ah[g], bl[2], bl[3]);
            }
        }
        __syncthreads();
    }

    // Epilogue: D frag (m16n8): d0,d1 -> (row, c0/c0+1); d2,d3 -> (row+8, ...)
    const int row = lane >> 2;
    const int c0  = (lane & 3) * 2;
    float rd0[4], rd1[4];
#pragma unroll
    for (int g = 0; g < 4; g++) {
        rd0[g] = g_rdenom[n * Mm + 16 * g + row];
        rd1[g] = g_rdenom[n * Mm + 16 * g + row + 8];
    }
#pragma unroll
    for (int b = 0; b < 2; b++) {
        float* __restrict__ og =
            out + (size_t)(((2 * bp + b) * Nn + n) * Mm) * Ff;
#pragma unroll
        for (int g = 0; g < 4; g++) {
#pragma unroll
            for (int j = 0; j < 2; j++) {
                const int f = 16 * w + 8 * j + c0;
                float2 p0, p1;
                p0.x = acc[b][g][j][0] * rd0[g];
                p0.y = acc[b][g][j][1] * rd0[g];
                p1.x = acc[b][g][j][2] * rd1[g];
                p1.y = acc[b][g][j][3] * rd1[g];
                *(float2*)&og[(16 * g + row) * Ff + f]     = p0;
                *(float2*)&og[(16 * g + row + 8) * Ff + f] = p1;
            }
        }
    }
}

// ---------------------------------------------------------------------------
// Launch: alpha -> denom -> gemm (sequential, graph-capturable)
// Inputs (metadata order): x_aug, t, t_left, t_right, kappa
// ---------------------------------------------------------------------------
extern "C" void kernel_launch(void* const* d_in, const int* in_sizes, int n_in,
                              void* d_out, int out_size)
{
    (void)in_sizes; (void)n_in; (void)out_size;
    const float* x       = (const float*)d_in[0];
    const float* t       = (const float*)d_in[1];
    const float* t_left  = (const float*)d_in[2];
    const float* t_right = (const float*)d_in[3];
    const float* kappa   = (const float*)d_in[4];
    float* out = (float*)d_out;

    alpha_kernel<<<dim3(8, Nn), 256>>>(t, t_left, t_right, kappa);
    denom_kernel<<<Nn, 256>>>();
    gemm_kernel<<<dim3(Bb / 2, Nn), 128>>>(x, out);
}